// round 5
// baseline (speedup 1.0000x reference)
#include <cuda_runtime.h>
#include <math.h>

namespace {
constexpr int Bc = 4, Sc = 1024, Ec = 512, Hc = 8, DKc = 64;
constexpr int M_TOT = Bc * Sc;  // 4096
}

// Scratch (device globals: allocation-free per harness rules)
__device__ float g_Q[(size_t)Bc * Hc * Sc * DKc];
__device__ float g_K[(size_t)Bc * Hc * Sc * DKc];
__device__ float g_V[(size_t)Bc * Hc * Sc * DKc];
__device__ float g_X[(size_t)Bc * Sc * Ec];

// ---- packed fp32x2 helpers (B300 FFMA2: only reachable via PTX) ------------
__device__ __forceinline__ void fma2(unsigned long long& d, unsigned long long a,
                                     unsigned long long b) {
    asm("fma.rn.f32x2 %0, %1, %2, %0;" : "+l"(d) : "l"(a), "l"(b));
}
__device__ __forceinline__ void mul2(unsigned long long& d, unsigned long long a) {
    asm("mul.rn.f32x2 %0, %0, %1;" : "+l"(d) : "l"(a), "l"(a));
}
__device__ __forceinline__ unsigned long long bc2(float x) {
    unsigned long long r;
    asm("mov.b64 %0, {%1, %1};" : "=l"(r) : "f"(x));
    return r;
}
__device__ __forceinline__ float2 up2(unsigned long long v) {
    float2 f;
    asm("mov.b64 {%0, %1}, %2;" : "=f"(f.x), "=f"(f.y) : "l"(v));
    return f;
}

// ---- cp.async helpers ------------------------------------------------------
__device__ __forceinline__ void cpa16(void* smem_dst, const void* gsrc) {
    unsigned s = (unsigned)__cvta_generic_to_shared(smem_dst);
    asm volatile("cp.async.cg.shared.global [%0], [%1], 16;" :: "r"(s), "l"(gsrc));
}
__device__ __forceinline__ void cpa_commit() {
    asm volatile("cp.async.commit_group;" ::: "memory");
}
__device__ __forceinline__ void cpa_wait0() {
    asm volatile("cp.async.wait_group 0;" ::: "memory");
}

// chunk swizzle keyed on r>>2: rows accessed together (stride-4 rows) get
// distinct 16B chunk positions -> minimum-phase LDS.128 for row AND
// column-of-rows access.
__device__ __forceinline__ int SWZ(int r, int c) { return c ^ (((r >> 2) & 7) << 2); }

// ---------------------------------------------------------------------------
// GEMM: Y = X * W^T + bias.  X:[M,E], W:[N,K]=[E,E] row-major.
// Tile 128m x 64n, BK=32, micro 8x4, k-parity packed FFMA2 accumulators.
// Double-buffered cp.async stages. Dynamic smem: 2*(128*32) + 2*(64*32) fl.
// ---------------------------------------------------------------------------
template <bool SPLIT>
__device__ __forceinline__ void gemm_body(const float* __restrict__ X,
                                          const float* __restrict__ W,
                                          const float* __restrict__ bias,
                                          float* __restrict__ Y) {
    extern __shared__ float smg[];
    float* Xs[2] = {smg, smg + 4096};
    float* Ws[2] = {smg + 8192, smg + 8192 + 2048};

    const int tid = threadIdx.x;
    const int tx = tid & 15, ty = tid >> 4;
    const int bm = blockIdx.y * 128, bn = blockIdx.x * 64;

    // stage one BK=32 slab of X (128x32) and W (64x32) into buffer bf
    auto stage = [&](int k0, int bf) {
#pragma unroll
        for (int t = 0; t < 4; t++) {  // X: 1024 float4 slots
            int idx = t * 256 + tid;
            int r = idx >> 3, c = (idx & 7) << 2;
            cpa16(&Xs[bf][r * 32 + SWZ(r, c)], &X[(size_t)(bm + r) * Ec + k0 + c]);
        }
#pragma unroll
        for (int t = 0; t < 2; t++) {  // W: 512 float4 slots
            int idx = t * 256 + tid;
            int r = idx >> 3, c = (idx & 7) << 2;
            cpa16(&Ws[bf][r * 32 + SWZ(r, c)], &W[(size_t)(bn + r) * Ec + k0 + c]);
        }
    };

    unsigned long long acc[8][4] = {};

    stage(0, 0);
    cpa_commit();
    cpa_wait0();
    __syncthreads();

    int bf = 0;
    for (int ks = 0; ks < Ec / 32; ks++) {
        if (ks + 1 < Ec / 32) {
            stage((ks + 1) * 32, bf ^ 1);
            cpa_commit();
        }
        const float* Xc = Xs[bf];
        const float* Wc = Ws[bf];
#pragma unroll
        for (int kc = 0; kc < 8; kc++) {
            const int k = kc * 4;
            ulonglong2 a[8], w[4];
#pragma unroll
            for (int i = 0; i < 8; i++) {
                const int r = ty * 8 + i;
                a[i] = *(const ulonglong2*)&Xc[r * 32 + SWZ(r, k)];
            }
#pragma unroll
            for (int j = 0; j < 4; j++) {
                const int r = tx * 4 + j;
                w[j] = *(const ulonglong2*)&Wc[r * 32 + SWZ(r, k)];
            }
#pragma unroll
            for (int i = 0; i < 8; i++)
#pragma unroll
                for (int j = 0; j < 4; j++) {
                    fma2(acc[i][j], a[i].x, w[j].x);
                    fma2(acc[i][j], a[i].y, w[j].y);
                }
        }
        cpa_wait0();
        __syncthreads();
        bf ^= 1;
    }

    const int n0 = bn + tx * 4;
    const float4 bv = *(const float4*)&bias[n0];
#pragma unroll
    for (int i = 0; i < 8; i++) {
        const int m = bm + ty * 8 + i;
        float2 p0 = up2(acc[i][0]), p1 = up2(acc[i][1]);
        float2 p2 = up2(acc[i][2]), p3 = up2(acc[i][3]);
        float4 o;
        o.x = p0.x + p0.y + bv.x;
        o.y = p1.x + p1.y + bv.y;
        o.z = p2.x + p2.y + bv.z;
        o.w = p3.x + p3.y + bv.w;
        if (SPLIT) {
            const int bIdx = m >> 10, s = m & (Sc - 1);
            const int h = n0 >> 6, d = n0 & 63;
            *(float4*)&Y[(((size_t)bIdx * Hc + h) * Sc + s) * DKc + d] = o;
        } else {
            *(float4*)&Y[(size_t)m * Ec + n0] = o;
        }
    }
}

// fused Q/K/V projections: blockIdx.z selects which projection
__global__ void __launch_bounds__(256, 2) gemm_qkv(
    const float* __restrict__ Xq, const float* __restrict__ Xk,
    const float* __restrict__ Xv, const float* __restrict__ Wq,
    const float* __restrict__ Wk, const float* __restrict__ Wv,
    const float* __restrict__ bq, const float* __restrict__ bk,
    const float* __restrict__ bv, float* __restrict__ Yq, float* __restrict__ Yk,
    float* __restrict__ Yv) {
    const int z = blockIdx.z;
    const float* X = (z == 0) ? Xq : (z == 1) ? Xk : Xv;
    const float* W = (z == 0) ? Wq : (z == 1) ? Wk : Wv;
    const float* b = (z == 0) ? bq : (z == 1) ? bk : bv;
    float* Y = (z == 0) ? Yq : (z == 1) ? Yk : Yv;
    gemm_body<true>(X, W, b, Y);
}

__global__ void __launch_bounds__(256, 2) gemm_out(const float* __restrict__ X,
                                                   const float* __restrict__ W,
                                                   const float* __restrict__ bias,
                                                   float* __restrict__ Y) {
    gemm_body<false>(X, W, bias, Y);
}

// ---------------------------------------------------------------------------
// Fused flash attention (round-2 compute structure) + cp.async double-buffered
// K/V tiles (one __syncthreads per k-tile instead of two).
// Dynamic smem floats: Qs 4096 | K0 4096 | V0 4096 | K1 4096 | V1 4096 | Ps 4096
// = 24576 floats = 96 KB.
// ---------------------------------------------------------------------------
__global__ void __launch_bounds__(256, 2) attn_kernel(
    const float* __restrict__ Qp, const float* __restrict__ Kp,
    const float* __restrict__ Vp, const float* __restrict__ dist,
    const int* __restrict__ mask, const float* __restrict__ cw1,
    const float* __restrict__ cb1, const float* __restrict__ cw2,
    const float* __restrict__ cb2, float* __restrict__ Xout) {
    extern __shared__ float sm[];
    float* Qs = sm;
    float* Kb[2] = {sm + 4096, sm + 12288};
    float* Vb[2] = {sm + 8192, sm + 16384};
    float* Ps = sm + 20480;

    const int tid = threadIdx.x;
    const int tx = tid & 15, ty = tid >> 4;
    const int b = blockIdx.z, h = blockIdx.x;
    const int q0 = blockIdx.y * 64;

    const float* Qbase = Qp + ((size_t)b * Hc + h) * Sc * DKc;
    const float* Kbase = Kp + ((size_t)b * Hc + h) * Sc * DKc;
    const float* Vbase = Vp + ((size_t)b * Hc + h) * Sc * DKc;

    float w1[8], b1[8], w2[8];
#pragma unroll
    for (int t = 0; t < 8; t++) {
        w1[t] = cw1[t];
        b1[t] = cb1[t];
        w2[t] = cw2[h * Hc + t];
    }
    const float c2 = cb2[h];

    auto stage_kv = [&](int k0, int bf) {
#pragma unroll
        for (int t = 0; t < 4; t++) {
            int idx = t * 256 + tid;
            int r = idx >> 4, c = (idx & 15) << 2;
            cpa16(&Kb[bf][r * 64 + SWZ(r, c)], &Kbase[(size_t)(k0 + r) * DKc + c]);
            cpa16(&Vb[bf][r * 64 + SWZ(r, c)], &Vbase[(size_t)(k0 + r) * DKc + c]);
        }
    };

    // stage first K/V tile; load Q tile with plain LDG->STS meanwhile
    stage_kv(0, 0);
    cpa_commit();
#pragma unroll
    for (int t = 0; t < 4; t++) {
        int idx = t * 256 + tid;
        int r = idx >> 4, c = (idx & 15) << 2;
        *(float4*)&Qs[r * 64 + SWZ(r, c)] =
            *(const float4*)&Qbase[(size_t)(q0 + r) * DKc + c];
    }

    unsigned long long o[4][2] = {};  // packed over output columns
    float mrow[4], lrow[4];
#pragma unroll
    for (int i = 0; i < 4; i++) { mrow[i] = -INFINITY; lrow[i] = 0.f; }

    cpa_wait0();
    __syncthreads();

    int bf = 0;
    for (int k0 = 0; k0 < Sc; k0 += 64) {
        if (k0 + 64 < Sc) {
            stage_kv(k0 + 64, bf ^ 1);
            cpa_commit();
        }
        const float* Ks = Kb[bf];
        const float* Vs = Vb[bf];

        // S = Q * K^T : packed over k-parity
        float sc[4][4];
        {
            unsigned long long qk[4][4] = {};
#pragma unroll
            for (int k = 0; k < DKc; k += 4) {
                ulonglong2 aq[4], kk[4];
#pragma unroll
                for (int i = 0; i < 4; i++) {
                    const int r = ty * 4 + i;
                    aq[i] = *(const ulonglong2*)&Qs[r * 64 + SWZ(r, k)];
                }
#pragma unroll
                for (int j = 0; j < 4; j++) {
                    const int r = tx * 4 + j;
                    kk[j] = *(const ulonglong2*)&Ks[r * 64 + SWZ(r, k)];
                }
#pragma unroll
                for (int i = 0; i < 4; i++)
#pragma unroll
                    for (int j = 0; j < 4; j++) {
                        fma2(qk[i][j], aq[i].x, kk[j].x);
                        fma2(qk[i][j], aq[i].y, kk[j].y);
                    }
            }
#pragma unroll
            for (int i = 0; i < 4; i++)
#pragma unroll
                for (int j = 0; j < 4; j++) {
                    float2 f = up2(qk[i][j]);
                    sc[i][j] = f.x + f.y;
                }
        }

        // scale * bias, mask
#pragma unroll
        for (int i = 0; i < 4; i++) {
            const int qi = q0 + ty * 4 + i;
            const size_t rowoff = ((size_t)b * Sc + qi) * Sc + k0 + tx * 4;
            float4 dv = *(const float4*)&dist[rowoff];
            int4 mv = *(const int4*)&mask[rowoff];
            float dd[4] = {dv.x, dv.y, dv.z, dv.w};
            int mm[4] = {mv.x, mv.y, mv.z, mv.w};
#pragma unroll
            for (int j = 0; j < 4; j++) {
                float bias = c2;
#pragma unroll
                for (int t = 0; t < 8; t++)
                    bias += w2[t] * fmaxf(fmaf(dd[j], w1[t], b1[t]), 0.f);
                float sv = sc[i][j] * 0.125f * bias;
                sc[i][j] = (mm[j] == 0) ? -1e9f : sv;
            }
        }

        // online softmax; rows live in one 16-lane group
#pragma unroll
        for (int i = 0; i < 4; i++) {
            float mloc = fmaxf(fmaxf(sc[i][0], sc[i][1]), fmaxf(sc[i][2], sc[i][3]));
#pragma unroll
            for (int off = 8; off >= 1; off >>= 1)
                mloc = fmaxf(mloc, __shfl_xor_sync(0xffffffffu, mloc, off, 16));
            const float mnew = fmaxf(mrow[i], mloc);
            const float alpha = __expf(mrow[i] - mnew);
            mrow[i] = mnew;
            float p0 = __expf(sc[i][0] - mnew);
            float p1 = __expf(sc[i][1] - mnew);
            float p2 = __expf(sc[i][2] - mnew);
            float p3 = __expf(sc[i][3] - mnew);
            float rs = (p0 + p1) + (p2 + p3);
#pragma unroll
            for (int off = 8; off >= 1; off >>= 1)
                rs += __shfl_xor_sync(0xffffffffu, rs, off, 16);
            lrow[i] = lrow[i] * alpha + rs;
            float4 pv = {p0, p1, p2, p3};
            const int r = ty * 4 + i;
            *(float4*)&Ps[r * 64 + SWZ(r, tx * 4)] = pv;
            unsigned long long av = bc2(alpha);
            mul2(o[i][0], av);
            mul2(o[i][1], av);
        }
        __syncwarp(0xffffffffu);  // P tile produced/consumed half-warp-locally

        // O += P * V : packed over output columns
#pragma unroll
        for (int k = 0; k < 64; k += 4) {
            ulonglong2 pr[4], vv[4];
#pragma unroll
            for (int i = 0; i < 4; i++) {
                const int r = ty * 4 + i;
                pr[i] = *(const ulonglong2*)&Ps[r * 64 + SWZ(r, k)];
            }
#pragma unroll
            for (int u = 0; u < 4; u++)
                vv[u] = *(const ulonglong2*)&Vs[(k + u) * 64 + SWZ(k + u, tx * 4)];
#pragma unroll
            for (int i = 0; i < 4; i++) {
                float2 p01 = up2(pr[i].x);
                float2 p23 = up2(pr[i].y);
                unsigned long long w0 = bc2(p01.x), w1p = bc2(p01.y);
                unsigned long long w2p = bc2(p23.x), w3 = bc2(p23.y);
                fma2(o[i][0], w0, vv[0].x);  fma2(o[i][1], w0, vv[0].y);
                fma2(o[i][0], w1p, vv[1].x); fma2(o[i][1], w1p, vv[1].y);
                fma2(o[i][0], w2p, vv[2].x); fma2(o[i][1], w2p, vv[2].y);
                fma2(o[i][0], w3, vv[3].x);  fma2(o[i][1], w3, vv[3].y);
            }
        }
        cpa_wait0();
        __syncthreads();
        bf ^= 1;
    }

    // epilogue: normalize, write concatenated [B,S,E]
#pragma unroll
    for (int i = 0; i < 4; i++) {
        const int qi = q0 + ty * 4 + i;
        const float inv = 1.f / lrow[i];
        float2 o01 = up2(o[i][0]);
        float2 o23 = up2(o[i][1]);
        float4 ov = {o01.x * inv, o01.y * inv, o23.x * inv, o23.y * inv};
        *(float4*)&Xout[((size_t)b * Sc + qi) * Ec + h * DKc + tx * 4] = ov;
    }
}

// ---------------------------------------------------------------------------

extern "C" void kernel_launch(void* const* d_in, const int* in_sizes, int n_in,
                              void* d_out, int out_size) {
    const float* query = (const float*)d_in[0];
    const float* key   = (const float*)d_in[1];
    const float* value = (const float*)d_in[2];
    const float* dist  = (const float*)d_in[3];
    const int*   mask  = (const int*)d_in[4];
    const float* Wq = (const float*)d_in[5];
    const float* bq = (const float*)d_in[6];
    const float* Wk = (const float*)d_in[7];
    const float* bk = (const float*)d_in[8];
    const float* Wv = (const float*)d_in[9];
    const float* bv = (const float*)d_in[10];
    const float* Wo = (const float*)d_in[11];
    const float* bo = (const float*)d_in[12];
    const float* cw1 = (const float*)d_in[13];
    const float* cb1 = (const float*)d_in[14];
    const float* cw2 = (const float*)d_in[15];
    const float* cb2 = (const float*)d_in[16];
    float* out = (float*)d_out;

    float *Qp, *Kp, *Vp, *Xc;
    cudaGetSymbolAddress((void**)&Qp, g_Q);
    cudaGetSymbolAddress((void**)&Kp, g_K);
    cudaGetSymbolAddress((void**)&Vp, g_V);
    cudaGetSymbolAddress((void**)&Xc, g_X);

    const int gsmem = (2 * 4096 + 2 * 2048) * (int)sizeof(float);  // 48 KB
    cudaFuncSetAttribute(gemm_qkv, cudaFuncAttributeMaxDynamicSharedMemorySize, gsmem);
    cudaFuncSetAttribute(gemm_out, cudaFuncAttributeMaxDynamicSharedMemorySize, gsmem);

    gemm_qkv<<<dim3(Ec / 64, M_TOT / 128, 3), 256, gsmem>>>(
        query, key, value, Wq, Wk, Wv, bq, bk, bv, Qp, Kp, Vp);

    const int asmem = 24576 * (int)sizeof(float);  // 96 KB
    cudaFuncSetAttribute(attn_kernel, cudaFuncAttributeMaxDynamicSharedMemorySize, asmem);
    attn_kernel<<<dim3(Hc, Sc / 64, Bc), 256, asmem>>>(Qp, Kp, Vp, dist, mask, cw1,
                                                       cb1, cw2, cb2, Xc);

    gemm_out<<<dim3(Ec / 64, M_TOT / 128, 1), 256, gsmem>>>(Xc, Wo, bo, out);
}

// round 6
// speedup vs baseline: 1.4884x; 1.4884x over previous
#include <cuda_runtime.h>
#include <math.h>

namespace {
constexpr int Bc = 4, Sc = 1024, Ec = 512, Hc = 8, DKc = 64;
constexpr int M_TOT = Bc * Sc;  // 4096
}

// Scratch (device globals: allocation-free per harness rules)
__device__ float g_Q[(size_t)Bc * Hc * Sc * DKc];
__device__ float g_K[(size_t)Bc * Hc * Sc * DKc];
__device__ float g_V[(size_t)Bc * Hc * Sc * DKc];
__device__ float g_X[(size_t)Bc * Sc * Ec];

// ---- packed fp32x2 helpers (B300 FFMA2: only reachable via PTX) ------------
__device__ __forceinline__ void fma2(unsigned long long& d, unsigned long long a,
                                     unsigned long long b) {
    asm("fma.rn.f32x2 %0, %1, %2, %0;" : "+l"(d) : "l"(a), "l"(b));
}
__device__ __forceinline__ void mul2(unsigned long long& d, unsigned long long a) {
    asm("mul.rn.f32x2 %0, %0, %1;" : "+l"(d) : "l"(a));
}
__device__ __forceinline__ unsigned long long bc2(float x) {
    unsigned long long r;
    asm("mov.b64 %0, {%1, %1};" : "=l"(r) : "f"(x));
    return r;
}
__device__ __forceinline__ float2 up2(unsigned long long v) {
    float2 f;
    asm("mov.b64 {%0, %1}, %2;" : "=f"(f.x), "=f"(f.y) : "l"(v));
    return f;
}

// chunk swizzle: 16B chunks XORed by row bits -> conflict-free (2-phase min)
// LDS.128 for row-broadcast AND column-of-rows access in [*][64] fp32 tiles.
__device__ __forceinline__ int SWZ(int r, int c) { return c ^ (((r >> 2) & 7) << 2); }

// ---------------------------------------------------------------------------
// GEMM: Y = X * W^T + bias.  X:[M,E], W:[N,K]=[E,E] row-major.
// Tile 128m x 64n, BK=64, 256 threads, 8x4 micro-tile, k-parity FFMA2.
// Plain LDG->STS staging (L1-cached: W tiles are reused by 32 M-blocks),
// single smem buffer. Dynamic smem: (128+64)*64 floats = 48 KB.
// ---------------------------------------------------------------------------
template <bool SPLIT>
__device__ __forceinline__ void gemm_body(const float* __restrict__ X,
                                          const float* __restrict__ W,
                                          const float* __restrict__ bias,
                                          float* __restrict__ Y) {
    extern __shared__ float smg[];
    float* Xs = smg;          // [128][64] swizzled
    float* Ws = smg + 8192;   // [64][64]  swizzled

    const int tid = threadIdx.x;
    const int tx = tid & 15, ty = tid >> 4;
    const int bm = blockIdx.y * 128, bn = blockIdx.x * 64;

    unsigned long long acc[8][4] = {};

    for (int k0 = 0; k0 < Ec; k0 += 64) {
#pragma unroll
        for (int t = 0; t < 8; t++) {  // X: 2048 float4 slots
            int idx = t * 256 + tid;
            int r = idx >> 4, c = (idx & 15) << 2;
            *(float4*)&Xs[r * 64 + SWZ(r, c)] =
                *(const float4*)&X[(size_t)(bm + r) * Ec + k0 + c];
        }
#pragma unroll
        for (int t = 0; t < 4; t++) {  // W: 1024 float4 slots
            int idx = t * 256 + tid;
            int r = idx >> 4, c = (idx & 15) << 2;
            *(float4*)&Ws[r * 64 + SWZ(r, c)] =
                *(const float4*)&W[(size_t)(bn + r) * Ec + k0 + c];
        }
        __syncthreads();
#pragma unroll
        for (int kc = 0; kc < 16; kc++) {
            const int k = kc * 4;
            ulonglong2 a[8], w[4];
#pragma unroll
            for (int j = 0; j < 4; j++) {
                const int r = tx * 4 + j;
                w[j] = *(const ulonglong2*)&Ws[r * 64 + SWZ(r, k)];
            }
#pragma unroll
            for (int i = 0; i < 8; i++) {
                const int r = ty * 8 + i;
                a[i] = *(const ulonglong2*)&Xs[r * 64 + SWZ(r, k)];
            }
#pragma unroll
            for (int i = 0; i < 8; i++)
#pragma unroll
                for (int j = 0; j < 4; j++) {
                    fma2(acc[i][j], a[i].x, w[j].x);
                    fma2(acc[i][j], a[i].y, w[j].y);
                }
        }
        __syncthreads();
    }

    const int n0 = bn + tx * 4;
    const float4 bv = *(const float4*)&bias[n0];
#pragma unroll
    for (int i = 0; i < 8; i++) {
        const int m = bm + ty * 8 + i;
        float2 p0 = up2(acc[i][0]), p1 = up2(acc[i][1]);
        float2 p2 = up2(acc[i][2]), p3 = up2(acc[i][3]);
        float4 o;
        o.x = p0.x + p0.y + bv.x;
        o.y = p1.x + p1.y + bv.y;
        o.z = p2.x + p2.y + bv.z;
        o.w = p3.x + p3.y + bv.w;
        if (SPLIT) {
            const int bIdx = m >> 10, s = m & (Sc - 1);
            const int h = n0 >> 6, d = n0 & 63;
            *(float4*)&Y[(((size_t)bIdx * Hc + h) * Sc + s) * DKc + d] = o;
        } else {
            *(float4*)&Y[(size_t)m * Ec + n0] = o;
        }
    }
}

// fused Q/K/V projections: blockIdx.z selects which projection
__global__ void __launch_bounds__(256, 2) gemm_qkv(
    const float* __restrict__ Xq, const float* __restrict__ Xk,
    const float* __restrict__ Xv, const float* __restrict__ Wq,
    const float* __restrict__ Wk, const float* __restrict__ Wv,
    const float* __restrict__ bq, const float* __restrict__ bk,
    const float* __restrict__ bv, float* __restrict__ Yq, float* __restrict__ Yk,
    float* __restrict__ Yv) {
    const int z = blockIdx.z;
    const float* X = (z == 0) ? Xq : (z == 1) ? Xk : Xv;
    const float* W = (z == 0) ? Wq : (z == 1) ? Wk : Wv;
    const float* b = (z == 0) ? bq : (z == 1) ? bk : bv;
    float* Y = (z == 0) ? Yq : (z == 1) ? Yk : Yv;
    gemm_body<true>(X, W, b, Y);
}

__global__ void __launch_bounds__(256, 2) gemm_out(const float* __restrict__ X,
                                                   const float* __restrict__ W,
                                                   const float* __restrict__ bias,
                                                   float* __restrict__ Y) {
    gemm_body<false>(X, W, bias, Y);
}

// ---------------------------------------------------------------------------
// Fused flash attention (proven Round-2 version: FFMA2 + swizzled LDS.128,
// plain LDG->STS tile loads, two barriers per k-tile).
// grid: (h, q-tile, b). Dynamic smem: 4 * 64*64 floats = 64 KB.
// ---------------------------------------------------------------------------
__global__ void __launch_bounds__(256, 2) attn_kernel(
    const float* __restrict__ Qp, const float* __restrict__ Kp,
    const float* __restrict__ Vp, const float* __restrict__ dist,
    const int* __restrict__ mask, const float* __restrict__ cw1,
    const float* __restrict__ cb1, const float* __restrict__ cw2,
    const float* __restrict__ cb2, float* __restrict__ Xout) {
    extern __shared__ float sm[];
    float* Qs = sm;             // [64][64] swizzled
    float* Ks = sm + 4096;
    float* Vs = sm + 8192;
    float* Ps = sm + 12288;

    const int tid = threadIdx.x;
    const int tx = tid & 15, ty = tid >> 4;
    const int b = blockIdx.z, h = blockIdx.x;
    const int q0 = blockIdx.y * 64;

    const float* Qbase = Qp + ((size_t)b * Hc + h) * Sc * DKc;
    const float* Kbase = Kp + ((size_t)b * Hc + h) * Sc * DKc;
    const float* Vbase = Vp + ((size_t)b * Hc + h) * Sc * DKc;

    float w1[8], b1[8], w2[8];
#pragma unroll
    for (int t = 0; t < 8; t++) {
        w1[t] = cw1[t];
        b1[t] = cb1[t];
        w2[t] = cw2[h * Hc + t];
    }
    const float c2 = cb2[h];

    // load Q tile (64x64), swizzled
#pragma unroll
    for (int t = 0; t < 4; t++) {
        int idx = t * 256 + tid;
        int r = idx >> 4, c = (idx & 15) << 2;
        *(float4*)&Qs[r * 64 + SWZ(r, c)] =
            *(const float4*)&Qbase[(size_t)(q0 + r) * DKc + c];
    }

    unsigned long long o[4][2] = {};  // packed over output columns
    float mrow[4], lrow[4];
#pragma unroll
    for (int i = 0; i < 4; i++) { mrow[i] = -INFINITY; lrow[i] = 0.f; }

    for (int k0 = 0; k0 < Sc; k0 += 64) {
        __syncthreads();  // prior-iter Ks/Vs reads complete (also covers Q load)
#pragma unroll
        for (int t = 0; t < 4; t++) {
            int idx = t * 256 + tid;
            int r = idx >> 4, c = (idx & 15) << 2;
            *(float4*)&Ks[r * 64 + SWZ(r, c)] =
                *(const float4*)&Kbase[(size_t)(k0 + r) * DKc + c];
            *(float4*)&Vs[r * 64 + SWZ(r, c)] =
                *(const float4*)&Vbase[(size_t)(k0 + r) * DKc + c];
        }
        __syncthreads();

        // S = Q * K^T : packed over k-parity
        float sc[4][4];
        {
            unsigned long long qk[4][4] = {};
#pragma unroll
            for (int k = 0; k < DKc; k += 4) {
                ulonglong2 aq[4], kk[4];
#pragma unroll
                for (int i = 0; i < 4; i++) {
                    const int r = ty * 4 + i;
                    aq[i] = *(const ulonglong2*)&Qs[r * 64 + SWZ(r, k)];
                }
#pragma unroll
                for (int j = 0; j < 4; j++) {
                    const int r = tx * 4 + j;
                    kk[j] = *(const ulonglong2*)&Ks[r * 64 + SWZ(r, k)];
                }
#pragma unroll
                for (int i = 0; i < 4; i++)
#pragma unroll
                    for (int j = 0; j < 4; j++) {
                        fma2(qk[i][j], aq[i].x, kk[j].x);
                        fma2(qk[i][j], aq[i].y, kk[j].y);
                    }
            }
#pragma unroll
            for (int i = 0; i < 4; i++)
#pragma unroll
                for (int j = 0; j < 4; j++) {
                    float2 f = up2(qk[i][j]);
                    sc[i][j] = f.x + f.y;
                }
        }

        // scale * bias, mask
#pragma unroll
        for (int i = 0; i < 4; i++) {
            const int qi = q0 + ty * 4 + i;
            const size_t rowoff = ((size_t)b * Sc + qi) * Sc + k0 + tx * 4;
            float4 dv = *(const float4*)&dist[rowoff];
            int4 mv = *(const int4*)&mask[rowoff];
            float dd[4] = {dv.x, dv.y, dv.z, dv.w};
            int mm[4] = {mv.x, mv.y, mv.z, mv.w};
#pragma unroll
            for (int j = 0; j < 4; j++) {
                float bias = c2;
#pragma unroll
                for (int t = 0; t < 8; t++)
                    bias += w2[t] * fmaxf(fmaf(dd[j], w1[t], b1[t]), 0.f);
                float sv = sc[i][j] * 0.125f * bias;
                sc[i][j] = (mm[j] == 0) ? -1e9f : sv;
            }
        }

        // online softmax; rows live in one 16-lane group
#pragma unroll
        for (int i = 0; i < 4; i++) {
            float mloc = fmaxf(fmaxf(sc[i][0], sc[i][1]), fmaxf(sc[i][2], sc[i][3]));
#pragma unroll
            for (int off = 8; off >= 1; off >>= 1)
                mloc = fmaxf(mloc, __shfl_xor_sync(0xffffffffu, mloc, off, 16));
            const float mnew = fmaxf(mrow[i], mloc);
            const float alpha = __expf(mrow[i] - mnew);
            mrow[i] = mnew;
            float p0 = __expf(sc[i][0] - mnew);
            float p1 = __expf(sc[i][1] - mnew);
            float p2 = __expf(sc[i][2] - mnew);
            float p3 = __expf(sc[i][3] - mnew);
            float rs = (p0 + p1) + (p2 + p3);
#pragma unroll
            for (int off = 8; off >= 1; off >>= 1)
                rs += __shfl_xor_sync(0xffffffffu, rs, off, 16);
            lrow[i] = lrow[i] * alpha + rs;
            float4 pv = {p0, p1, p2, p3};
            const int r = ty * 4 + i;
            *(float4*)&Ps[r * 64 + SWZ(r, tx * 4)] = pv;
            unsigned long long av = bc2(alpha);
            mul2(o[i][0], av);
            mul2(o[i][1], av);
        }
        __syncwarp(0xffffffffu);  // P tile produced/consumed warp-locally

        // O += P * V : packed over output columns
#pragma unroll
        for (int k = 0; k < 64; k += 4) {
            ulonglong2 pr[4], vv[4];
#pragma unroll
            for (int i = 0; i < 4; i++) {
                const int r = ty * 4 + i;
                pr[i] = *(const ulonglong2*)&Ps[r * 64 + SWZ(r, k)];
            }
#pragma unroll
            for (int u = 0; u < 4; u++)
                vv[u] = *(const ulonglong2*)&Vs[(k + u) * 64 + SWZ(k + u, tx * 4)];
#pragma unroll
            for (int i = 0; i < 4; i++) {
                float2 p01 = up2(pr[i].x);
                float2 p23 = up2(pr[i].y);
                unsigned long long w0 = bc2(p01.x), w1p = bc2(p01.y);
                unsigned long long w2p = bc2(p23.x), w3 = bc2(p23.y);
                fma2(o[i][0], w0, vv[0].x);  fma2(o[i][1], w0, vv[0].y);
                fma2(o[i][0], w1p, vv[1].x); fma2(o[i][1], w1p, vv[1].y);
                fma2(o[i][0], w2p, vv[2].x); fma2(o[i][1], w2p, vv[2].y);
                fma2(o[i][0], w3, vv[3].x);  fma2(o[i][1], w3, vv[3].y);
            }
        }
    }

    // epilogue: normalize, write concatenated [B,S,E]
#pragma unroll
    for (int i = 0; i < 4; i++) {
        const int qi = q0 + ty * 4 + i;
        const float inv = 1.f / lrow[i];
        float2 o01 = up2(o[i][0]);
        float2 o23 = up2(o[i][1]);
        float4 ov = {o01.x * inv, o01.y * inv, o23.x * inv, o23.y * inv};
        *(float4*)&Xout[((size_t)b * Sc + qi) * Ec + h * DKc + tx * 4] = ov;
    }
}

// ---------------------------------------------------------------------------

extern "C" void kernel_launch(void* const* d_in, const int* in_sizes, int n_in,
                              void* d_out, int out_size) {
    const float* query = (const float*)d_in[0];
    const float* key   = (const float*)d_in[1];
    const float* value = (const float*)d_in[2];
    const float* dist  = (const float*)d_in[3];
    const int*   mask  = (const int*)d_in[4];
    const float* Wq = (const float*)d_in[5];
    const float* bq = (const float*)d_in[6];
    const float* Wk = (const float*)d_in[7];
    const float* bk = (const float*)d_in[8];
    const float* Wv = (const float*)d_in[9];
    const float* bv = (const float*)d_in[10];
    const float* Wo = (const float*)d_in[11];
    const float* bo = (const float*)d_in[12];
    const float* cw1 = (const float*)d_in[13];
    const float* cb1 = (const float*)d_in[14];
    const float* cw2 = (const float*)d_in[15];
    const float* cb2 = (const float*)d_in[16];
    float* out = (float*)d_out;

    float *Qp, *Kp, *Vp, *Xc;
    cudaGetSymbolAddress((void**)&Qp, g_Q);
    cudaGetSymbolAddress((void**)&Kp, g_K);
    cudaGetSymbolAddress((void**)&Vp, g_V);
    cudaGetSymbolAddress((void**)&Xc, g_X);

    const int gsmem = (8192 + 4096) * (int)sizeof(float);  // 48 KB
    cudaFuncSetAttribute(gemm_qkv, cudaFuncAttributeMaxDynamicSharedMemorySize, gsmem);
    cudaFuncSetAttribute(gemm_out, cudaFuncAttributeMaxDynamicSharedMemorySize, gsmem);

    gemm_qkv<<<dim3(Ec / 64, M_TOT / 128, 3), 256, gsmem>>>(
        query, key, value, Wq, Wk, Wv, bq, bk, bv, Qp, Kp, Vp);

    const int asmem = 4 * 4096 * (int)sizeof(float);  // 64 KB
    cudaFuncSetAttribute(attn_kernel, cudaFuncAttributeMaxDynamicSharedMemorySize, asmem);
    attn_kernel<<<dim3(Hc, Sc / 64, Bc), 256, asmem>>>(Qp, Kp, Vp, dist, mask, cw1,
                                                       cb1, cw2, cb2, Xc);

    gemm_out<<<dim3(Ec / 64, M_TOT / 128, 1), 256, gsmem>>>(Xc, Wo, bo, out);
}

// round 12
// speedup vs baseline: 2.1007x; 1.4114x over previous
#include <cuda_runtime.h>
#include <cuda_bf16.h>
#include <math.h>
#include <stdint.h>

namespace {
constexpr int Bc = 4, Sc = 1024, Ec = 512, Hc = 8, DKc = 64;
constexpr int M_TOT = Bc * Sc;  // 4096
}

// Scratch (device globals: allocation-free per harness rules)
__device__ float g_Q[(size_t)Bc * Hc * Sc * DKc];
__device__ float g_K[(size_t)Bc * Hc * Sc * DKc];
__device__ float g_V[(size_t)Bc * Hc * Sc * DKc];
__device__ float g_X[(size_t)Bc * Sc * Ec];

// ---- packed fp32x2 helpers (attention path) --------------------------------
__device__ __forceinline__ void fma2(unsigned long long& d, unsigned long long a,
                                     unsigned long long b) {
    asm("fma.rn.f32x2 %0, %1, %2, %0;" : "+l"(d) : "l"(a), "l"(b));
}
__device__ __forceinline__ void mul2(unsigned long long& d, unsigned long long a) {
    asm("mul.rn.f32x2 %0, %0, %1;" : "+l"(d) : "l"(a));
}
__device__ __forceinline__ unsigned long long bc2(float x) {
    unsigned long long r;
    asm("mov.b64 %0, {%1, %1};" : "=l"(r) : "f"(x));
    return r;
}
__device__ __forceinline__ float2 up2(unsigned long long v) {
    float2 f;
    asm("mov.b64 {%0, %1}, %2;" : "=f"(f.x), "=f"(f.y) : "l"(v));
    return f;
}

// chunk swizzle for attention fp32 tiles
__device__ __forceinline__ int SWZ(int r, int c) { return c ^ (((r >> 2) & 7) << 2); }

// ---- HMMA helpers (base sm_103 — no arch-specific features) ----------------
__device__ __forceinline__ unsigned smem_u32(const void* p) {
    return (unsigned)__cvta_generic_to_shared(p);
}
__device__ __forceinline__ void ldsm4(unsigned* r, unsigned addr) {
    asm volatile("ldmatrix.sync.aligned.m8n8.x4.shared.b16 {%0,%1,%2,%3}, [%4];"
                 : "=r"(r[0]), "=r"(r[1]), "=r"(r[2]), "=r"(r[3]) : "r"(addr));
}
__device__ __forceinline__ void ldsm2(unsigned* r, unsigned addr) {
    asm volatile("ldmatrix.sync.aligned.m8n8.x2.shared.b16 {%0,%1}, [%2];"
                 : "=r"(r[0]), "=r"(r[1]) : "r"(addr));
}
__device__ __forceinline__ void hmma(float* c, const unsigned* a, const unsigned* b) {
    asm volatile(
        "mma.sync.aligned.m16n8k16.row.col.f32.bf16.bf16.f32 "
        "{%0,%1,%2,%3}, {%4,%5,%6,%7}, {%8,%9}, {%0,%1,%2,%3};"
        : "+f"(c[0]), "+f"(c[1]), "+f"(c[2]), "+f"(c[3])
        : "r"(a[0]), "r"(a[1]), "r"(a[2]), "r"(a[3]), "r"(b[0]), "r"(b[1]));
}
// bf16 hi/lo split of two floats, each packed as bf16x2 words
__device__ __forceinline__ void split2(float a, float b, unsigned& hi, unsigned& lo) {
    __nv_bfloat16 ha = __float2bfloat16_rn(a), hb = __float2bfloat16_rn(b);
    __nv_bfloat16 la = __float2bfloat16_rn(a - __bfloat162float(ha));
    __nv_bfloat16 lb = __float2bfloat16_rn(b - __bfloat162float(hb));
    __nv_bfloat162 h2{ha, hb}, l2{la, lb};
    hi = *(unsigned*)&h2;
    lo = *(unsigned*)&l2;
}

// ---------------------------------------------------------------------------
// HMMA GEMM: Y = X * W^T + bias via bf16x3 split (element error ~2^-16).
// Tile 128m x 64n, BK=64; 8 warps as 2(m) x 4(n); warp tile 64m x 16n
// = 4x2 m16n8k16 tiles; 3 HMMA per tile per k16 (hi*hi, hi*lo, lo*hi).
// Smem tiles bf16, 128B rows, swizzle col ^ ((r&7)<<4) -> ldmatrix
// conflict-free.  Dynamic smem: Xhi 16K | Xlo 16K | Whi 8K | Wlo 8K = 48K.
// ---------------------------------------------------------------------------
template <bool SPLIT>
__device__ __forceinline__ void tgemm_body(const float* __restrict__ X,
                                           const float* __restrict__ W,
                                           const float* __restrict__ bias,
                                           float* __restrict__ Y) {
    extern __shared__ char sb[];
    char* Xhi = sb;
    char* Xlo = sb + 16384;
    char* Whi = sb + 32768;
    char* Wlo = sb + 40960;
    const unsigned sXh = smem_u32(Xhi), sXl = smem_u32(Xlo);
    const unsigned sWh = smem_u32(Whi), sWl = smem_u32(Wlo);

    const int tid = threadIdx.x, warp = tid >> 5, lane = tid & 31;
    const int wm = warp >> 2;   // 0..1 : 64-row slice
    const int wn = warp & 3;    // 0..3 : 16-col slice
    const int bm = blockIdx.y * 128, bn = blockIdx.x * 64;

    // ldmatrix per-thread addressing
    const int a_r = lane & 15;                 // row within 16-row tile
    const int a_cs = (lane >> 4) << 4;         // 0/16B: k chunk select
    const int b_r = lane & 7;                  // row within 8-row tile
    const int b_cs = ((lane >> 3) & 1) << 4;   // 0/16B

    float acc[4][2][4] = {};

    for (int ks = 0; ks < Ec / 64; ks++) {
        const int k0 = ks * 64;
        // stage X slab 128x64 -> bf16 hi/lo, swizzled
#pragma unroll
        for (int t = 0; t < 8; t++) {
            int idx = t * 256 + tid;
            int r = idx >> 4, c4 = (idx & 15) << 2;
            float4 v = *(const float4*)&X[(size_t)(bm + r) * Ec + k0 + c4];
            unsigned h0, l0, h1, l1;
            split2(v.x, v.y, h0, l0);
            split2(v.z, v.w, h1, l1);
            unsigned off = r * 128 + ((c4 * 2) ^ ((r & 7) << 4));
            *(uint2*)(Xhi + off) = make_uint2(h0, h1);
            *(uint2*)(Xlo + off) = make_uint2(l0, l1);
        }
        // stage W slab 64x64
#pragma unroll
        for (int t = 0; t < 4; t++) {
            int idx = t * 256 + tid;
            int r = idx >> 4, c4 = (idx & 15) << 2;
            float4 v = *(const float4*)&W[(size_t)(bn + r) * Ec + k0 + c4];
            unsigned h0, l0, h1, l1;
            split2(v.x, v.y, h0, l0);
            split2(v.z, v.w, h1, l1);
            unsigned off = r * 128 + ((c4 * 2) ^ ((r & 7) << 4));
            *(uint2*)(Whi + off) = make_uint2(h0, h1);
            *(uint2*)(Wlo + off) = make_uint2(l0, l1);
        }
        __syncthreads();

#pragma unroll
        for (int k = 0; k < 4; k++) {
            const int kb = k * 32;  // byte offset of this k16 step
            unsigned ah[4][4], al[4][4];
#pragma unroll
            for (int mt = 0; mt < 4; mt++) {
                const int row = wm * 64 + mt * 16 + a_r;
                const unsigned off =
                    row * 128 + ((kb + a_cs) ^ ((row & 7) << 4));
                ldsm4(ah[mt], sXh + off);
                ldsm4(al[mt], sXl + off);
            }
            unsigned bh[2][2], bl[2][2];
#pragma unroll
            for (int nt = 0; nt < 2; nt++) {
                const int row = wn * 16 + nt * 8 + b_r;
                const unsigned off =
                    row * 128 + ((kb + b_cs) ^ ((row & 7) << 4));
                ldsm2(bh[nt], sWh + off);
                ldsm2(bl[nt], sWl + off);
            }
#pragma unroll
            for (int mt = 0; mt < 4; mt++)
#pragma unroll
                for (int nt = 0; nt < 2; nt++) {
                    hmma(acc[mt][nt], ah[mt], bh[nt]);
                    hmma(acc[mt][nt], ah[mt], bl[nt]);
                    hmma(acc[mt][nt], al[mt], bh[nt]);
                }
        }
        __syncthreads();
    }

    // epilogue: D m16n8 layout -> thread (lane/4 row, (lane&3)*2 col pair)
    const int lr = lane >> 2, lc = (lane & 3) << 1;
#pragma unroll
    for (int mt = 0; mt < 4; mt++)
#pragma unroll
        for (int nt = 0; nt < 2; nt++) {
            const int ncol = wn * 16 + nt * 8 + lc;  // 0..63 within tile
            const float2 bv = *(const float2*)&bias[bn + ncol];
            const int m0 = bm + wm * 64 + mt * 16 + lr;
#pragma unroll
            for (int half = 0; half < 2; half++) {
                const int m = m0 + half * 8;
                float2 v;
                v.x = acc[mt][nt][half * 2 + 0] + bv.x;
                v.y = acc[mt][nt][half * 2 + 1] + bv.y;
                if (SPLIT) {
                    const int bIdx = m >> 10, s = m & (Sc - 1);
                    const int h = bn >> 6;
                    *(float2*)&Y[(((size_t)bIdx * Hc + h) * Sc + s) * DKc + ncol] = v;
                } else {
                    *(float2*)&Y[(size_t)m * Ec + bn + ncol] = v;
                }
            }
        }
}

// fused Q/K/V projections: blockIdx.z selects which projection
__global__ void __launch_bounds__(256, 2) gemm_qkv(
    const float* __restrict__ Xq, const float* __restrict__ Xk,
    const float* __restrict__ Xv, const float* __restrict__ Wq,
    const float* __restrict__ Wk, const float* __restrict__ Wv,
    const float* __restrict__ bq, const float* __restrict__ bk,
    const float* __restrict__ bv, float* __restrict__ Yq, float* __restrict__ Yk,
    float* __restrict__ Yv) {
    const int z = blockIdx.z;
    const float* X = (z == 0) ? Xq : (z == 1) ? Xk : Xv;
    const float* W = (z == 0) ? Wq : (z == 1) ? Wk : Wv;
    const float* b = (z == 0) ? bq : (z == 1) ? bk : bv;
    float* Y = (z == 0) ? Yq : (z == 1) ? Yk : Yv;
    tgemm_body<true>(X, W, b, Y);
}

__global__ void __launch_bounds__(256, 2) gemm_out(const float* __restrict__ X,
                                                   const float* __restrict__ W,
                                                   const float* __restrict__ bias,
                                                   float* __restrict__ Y) {
    tgemm_body<false>(X, W, bias, Y);
}

// ---------------------------------------------------------------------------
// Fused flash attention (proven Round-2 version: FFMA2 + swizzled LDS.128).
// grid: (h, q-tile, b). Dynamic smem: 4 * 64*64 floats = 64 KB.
// ---------------------------------------------------------------------------
__global__ void __launch_bounds__(256, 2) attn_kernel(
    const float* __restrict__ Qp, const float* __restrict__ Kp,
    const float* __restrict__ Vp, const float* __restrict__ dist,
    const int* __restrict__ mask, const float* __restrict__ cw1,
    const float* __restrict__ cb1, const float* __restrict__ cw2,
    const float* __restrict__ cb2, float* __restrict__ Xout) {
    extern __shared__ float sm[];
    float* Qs = sm;             // [64][64] swizzled
    float* Ks = sm + 4096;
    float* Vs = sm + 8192;
    float* Ps = sm + 12288;

    const int tid = threadIdx.x;
    const int tx = tid & 15, ty = tid >> 4;
    const int b = blockIdx.z, h = blockIdx.x;
    const int q0 = blockIdx.y * 64;

    const float* Qbase = Qp + ((size_t)b * Hc + h) * Sc * DKc;
    const float* Kbase = Kp + ((size_t)b * Hc + h) * Sc * DKc;
    const float* Vbase = Vp + ((size_t)b * Hc + h) * Sc * DKc;

    float w1[8], b1[8], w2[8];
#pragma unroll
    for (int t = 0; t < 8; t++) {
        w1[t] = cw1[t];
        b1[t] = cb1[t];
        w2[t] = cw2[h * Hc + t];
    }
    const float c2 = cb2[h];

#pragma unroll
    for (int t = 0; t < 4; t++) {
        int idx = t * 256 + tid;
        int r = idx >> 4, c = (idx & 15) << 2;
        *(float4*)&Qs[r * 64 + SWZ(r, c)] =
            *(const float4*)&Qbase[(size_t)(q0 + r) * DKc + c];
    }

    unsigned long long o[4][2] = {};
    float mrow[4], lrow[4];
#pragma unroll
    for (int i = 0; i < 4; i++) { mrow[i] = -INFINITY; lrow[i] = 0.f; }

    for (int k0 = 0; k0 < Sc; k0 += 64) {
        __syncthreads();
#pragma unroll
        for (int t = 0; t < 4; t++) {
            int idx = t * 256 + tid;
            int r = idx >> 4, c = (idx & 15) << 2;
            *(float4*)&Ks[r * 64 + SWZ(r, c)] =
                *(const float4*)&Kbase[(size_t)(k0 + r) * DKc + c];
            *(float4*)&Vs[r * 64 + SWZ(r, c)] =
                *(const float4*)&Vbase[(size_t)(k0 + r) * DKc + c];
        }
        __syncthreads();

        float sc[4][4];
        {
            unsigned long long qk[4][4] = {};
#pragma unroll
            for (int k = 0; k < DKc; k += 4) {
                ulonglong2 aq[4], kk[4];
#pragma unroll
                for (int i = 0; i < 4; i++) {
                    const int r = ty * 4 + i;
                    aq[i] = *(const ulonglong2*)&Qs[r * 64 + SWZ(r, k)];
                }
#pragma unroll
                for (int j = 0; j < 4; j++) {
                    const int r = tx * 4 + j;
                    kk[j] = *(const ulonglong2*)&Ks[r * 64 + SWZ(r, k)];
                }
#pragma unroll
                for (int i = 0; i < 4; i++)
#pragma unroll
                    for (int j = 0; j < 4; j++) {
                        fma2(qk[i][j], aq[i].x, kk[j].x);
                        fma2(qk[i][j], aq[i].y, kk[j].y);
                    }
            }
#pragma unroll
            for (int i = 0; i < 4; i++)
#pragma unroll
                for (int j = 0; j < 4; j++) {
                    float2 f = up2(qk[i][j]);
                    sc[i][j] = f.x + f.y;
                }
        }

#pragma unroll
        for (int i = 0; i < 4; i++) {
            const int qi = q0 + ty * 4 + i;
            const size_t rowoff = ((size_t)b * Sc + qi) * Sc + k0 + tx * 4;
            float4 dv = *(const float4*)&dist[rowoff];
            int4 mv = *(const int4*)&mask[rowoff];
            float dd[4] = {dv.x, dv.y, dv.z, dv.w};
            int mm[4] = {mv.x, mv.y, mv.z, mv.w};
#pragma unroll
            for (int j = 0; j < 4; j++) {
                float bias = c2;
#pragma unroll
                for (int t = 0; t < 8; t++)
                    bias += w2[t] * fmaxf(fmaf(dd[j], w1[t], b1[t]), 0.f);
                float sv = sc[i][j] * 0.125f * bias;
                sc[i][j] = (mm[j] == 0) ? -1e9f : sv;
            }
        }

#pragma unroll
        for (int i = 0; i < 4; i++) {
            float mloc = fmaxf(fmaxf(sc[i][0], sc[i][1]), fmaxf(sc[i][2], sc[i][3]));
#pragma unroll
            for (int off = 8; off >= 1; off >>= 1)
                mloc = fmaxf(mloc, __shfl_xor_sync(0xffffffffu, mloc, off, 16));
            const float mnew = fmaxf(mrow[i], mloc);
            const float alpha = __expf(mrow[i] - mnew);
            mrow[i] = mnew;
            float p0 = __expf(sc[i][0] - mnew);
            float p1 = __expf(sc[i][1] - mnew);
            float p2 = __expf(sc[i][2] - mnew);
            float p3 = __expf(sc[i][3] - mnew);
            float rs = (p0 + p1) + (p2 + p3);
#pragma unroll
            for (int off = 8; off >= 1; off >>= 1)
                rs += __shfl_xor_sync(0xffffffffu, rs, off, 16);
            lrow[i] = lrow[i] * alpha + rs;
            float4 pv = {p0, p1, p2, p3};
            const int r = ty * 4 + i;
            *(float4*)&Ps[r * 64 + SWZ(r, tx * 4)] = pv;
            unsigned long long av = bc2(alpha);
            mul2(o[i][0], av);
            mul2(o[i][1], av);
        }
        __syncwarp(0xffffffffu);

#pragma unroll
        for (int k = 0; k < 64; k += 4) {
            ulonglong2 pr[4], vv[4];
#pragma unroll
            for (int i = 0; i < 4; i++) {
                const int r = ty * 4 + i;
                pr[i] = *(const ulonglong2*)&Ps[r * 64 + SWZ(r, k)];
            }
#pragma unroll
            for (int u = 0; u < 4; u++)
                vv[u] = *(const ulonglong2*)&Vs[(k + u) * 64 + SWZ(k + u, tx * 4)];
#pragma unroll
            for (int i = 0; i < 4; i++) {
                float2 p01 = up2(pr[i].x);
                float2 p23 = up2(pr[i].y);
                unsigned long long w0 = bc2(p01.x), w1p = bc2(p01.y);
                unsigned long long w2p = bc2(p23.x), w3 = bc2(p23.y);
                fma2(o[i][0], w0, vv[0].x);  fma2(o[i][1], w0, vv[0].y);
                fma2(o[i][0], w1p, vv[1].x); fma2(o[i][1], w1p, vv[1].y);
                fma2(o[i][0], w2p, vv[2].x); fma2(o[i][1], w2p, vv[2].y);
                fma2(o[i][0], w3, vv[3].x);  fma2(o[i][1], w3, vv[3].y);
            }
        }
    }

#pragma unroll
    for (int i = 0; i < 4; i++) {
        const int qi = q0 + ty * 4 + i;
        const float inv = 1.f / lrow[i];
        float2 o01 = up2(o[i][0]);
        float2 o23 = up2(o[i][1]);
        float4 ov = {o01.x * inv, o01.y * inv, o23.x * inv, o23.y * inv};
        *(float4*)&Xout[((size_t)b * Sc + qi) * Ec + h * DKc + tx * 4] = ov;
    }
}

// ---------------------------------------------------------------------------

extern "C" void kernel_launch(void* const* d_in, const int* in_sizes, int n_in,
                              void* d_out, int out_size) {
    const float* query = (const float*)d_in[0];
    const float* key   = (const float*)d_in[1];
    const float* value = (const float*)d_in[2];
    const float* dist  = (const float*)d_in[3];
    const int*   mask  = (const int*)d_in[4];
    const float* Wq = (const float*)d_in[5];
    const float* bq = (const float*)d_in[6];
    const float* Wk = (const float*)d_in[7];
    const float* bk = (const float*)d_in[8];
    const float* Wv = (const float*)d_in[9];
    const float* bv = (const float*)d_in[10];
    const float* Wo = (const float*)d_in[11];
    const float* bo = (const float*)d_in[12];
    const float* cw1 = (const float*)d_in[13];
    const float* cb1 = (const float*)d_in[14];
    const float* cw2 = (const float*)d_in[15];
    const float* cb2 = (const float*)d_in[16];
    float* out = (float*)d_out;

    float *Qp, *Kp, *Vp, *Xc;
    cudaGetSymbolAddress((void**)&Qp, g_Q);
    cudaGetSymbolAddress((void**)&Kp, g_K);
    cudaGetSymbolAddress((void**)&Vp, g_V);
    cudaGetSymbolAddress((void**)&Xc, g_X);

    const int gsmem = 49152;  // bytes
    cudaFuncSetAttribute(gemm_qkv, cudaFuncAttributeMaxDynamicSharedMemorySize, gsmem);
    cudaFuncSetAttribute(gemm_out, cudaFuncAttributeMaxDynamicSharedMemorySize, gsmem);

    gemm_qkv<<<dim3(Ec / 64, M_TOT / 128, 3), 256, gsmem>>>(
        query, key, value, Wq, Wk, Wv, bq, bk, bv, Qp, Kp, Vp);

    const int asmem = 4 * 4096 * (int)sizeof(float);  // 64 KB
    cudaFuncSetAttribute(attn_kernel, cudaFuncAttributeMaxDynamicSharedMemorySize, asmem);
    attn_kernel<<<dim3(Hc, Sc / 64, Bc), 256, asmem>>>(Qp, Kp, Vp, dist, mask, cw1,
                                                       cb1, cw2, cb2, Xc);

    gemm_out<<<dim3(Ec / 64, M_TOT / 128, 1), 256, gsmem>>>(Xc, Wo, bo, out);
}

// round 13
// speedup vs baseline: 3.8302x; 1.8233x over previous
#include <cuda_runtime.h>
#include <cuda_bf16.h>
#include <math.h>
#include <stdint.h>

namespace {
constexpr int Bc = 4, Sc = 1024, Ec = 512, Hc = 8, DKc = 64;
constexpr int M_TOT = Bc * Sc;  // 4096
}

// Scratch (device globals: allocation-free per harness rules)
__device__ float g_Q[(size_t)Bc * Hc * Sc * DKc];
__device__ float g_K[(size_t)Bc * Hc * Sc * DKc];
__device__ float g_V[(size_t)Bc * Hc * Sc * DKc];
__device__ float g_X[(size_t)Bc * Sc * Ec];

// ---- HMMA helpers (base sm_103 — no arch-specific features) ----------------
__device__ __forceinline__ unsigned smem_u32(const void* p) {
    return (unsigned)__cvta_generic_to_shared(p);
}
__device__ __forceinline__ void ldsm4(unsigned* r, unsigned addr) {
    asm volatile("ldmatrix.sync.aligned.m8n8.x4.shared.b16 {%0,%1,%2,%3}, [%4];"
                 : "=r"(r[0]), "=r"(r[1]), "=r"(r[2]), "=r"(r[3]) : "r"(addr));
}
__device__ __forceinline__ void ldsm4t(unsigned* r, unsigned addr) {
    asm volatile("ldmatrix.sync.aligned.m8n8.x4.trans.shared.b16 {%0,%1,%2,%3}, [%4];"
                 : "=r"(r[0]), "=r"(r[1]), "=r"(r[2]), "=r"(r[3]) : "r"(addr));
}
__device__ __forceinline__ void ldsm2(unsigned* r, unsigned addr) {
    asm volatile("ldmatrix.sync.aligned.m8n8.x2.shared.b16 {%0,%1}, [%2];"
                 : "=r"(r[0]), "=r"(r[1]) : "r"(addr));
}
__device__ __forceinline__ void hmma(float* c, const unsigned* a, const unsigned* b) {
    asm volatile(
        "mma.sync.aligned.m16n8k16.row.col.f32.bf16.bf16.f32 "
        "{%0,%1,%2,%3}, {%4,%5,%6,%7}, {%8,%9}, {%0,%1,%2,%3};"
        : "+f"(c[0]), "+f"(c[1]), "+f"(c[2]), "+f"(c[3])
        : "r"(a[0]), "r"(a[1]), "r"(a[2]), "r"(a[3]), "r"(b[0]), "r"(b[1]));
}
// bf16 hi/lo split of two floats, each packed as bf16x2 words
__device__ __forceinline__ void split2(float a, float b, unsigned& hi, unsigned& lo) {
    __nv_bfloat16 ha = __float2bfloat16_rn(a), hb = __float2bfloat16_rn(b);
    __nv_bfloat16 la = __float2bfloat16_rn(a - __bfloat162float(ha));
    __nv_bfloat16 lb = __float2bfloat16_rn(b - __bfloat162float(hb));
    __nv_bfloat162 h2{ha, hb}, l2{la, lb};
    hi = *(unsigned*)&h2;
    lo = *(unsigned*)&l2;
}
// pack two f32 -> bf16x2 (lo in low half)
__device__ __forceinline__ unsigned pk2(float lo, float hi) {
    unsigned r;
    asm("cvt.rn.bf16x2.f32 %0, %1, %2;" : "=r"(r) : "f"(hi), "f"(lo));
    return r;
}

// ---------------------------------------------------------------------------
// HMMA GEMM: Y = X * W^T + bias via bf16x3 split (validated Round 12).
// ---------------------------------------------------------------------------
template <bool SPLIT>
__device__ __forceinline__ void tgemm_body(const float* __restrict__ X,
                                           const float* __restrict__ W,
                                           const float* __restrict__ bias,
                                           float* __restrict__ Y) {
    extern __shared__ char sb[];
    char* Xhi = sb;
    char* Xlo = sb + 16384;
    char* Whi = sb + 32768;
    char* Wlo = sb + 40960;
    const unsigned sXh = smem_u32(Xhi), sXl = smem_u32(Xlo);
    const unsigned sWh = smem_u32(Whi), sWl = smem_u32(Wlo);

    const int tid = threadIdx.x, warp = tid >> 5, lane = tid & 31;
    const int wm = warp >> 2;
    const int wn = warp & 3;
    const int bm = blockIdx.y * 128, bn = blockIdx.x * 64;

    const int a_r = lane & 15;
    const int a_cs = (lane >> 4) << 4;
    const int b_r = lane & 7;
    const int b_cs = ((lane >> 3) & 1) << 4;

    float acc[4][2][4] = {};

    for (int ks = 0; ks < Ec / 64; ks++) {
        const int k0 = ks * 64;
#pragma unroll
        for (int t = 0; t < 8; t++) {
            int idx = t * 256 + tid;
            int r = idx >> 4, c4 = (idx & 15) << 2;
            float4 v = *(const float4*)&X[(size_t)(bm + r) * Ec + k0 + c4];
            unsigned h0, l0, h1, l1;
            split2(v.x, v.y, h0, l0);
            split2(v.z, v.w, h1, l1);
            unsigned off = r * 128 + ((c4 * 2) ^ ((r & 7) << 4));
            *(uint2*)(Xhi + off) = make_uint2(h0, h1);
            *(uint2*)(Xlo + off) = make_uint2(l0, l1);
        }
#pragma unroll
        for (int t = 0; t < 4; t++) {
            int idx = t * 256 + tid;
            int r = idx >> 4, c4 = (idx & 15) << 2;
            float4 v = *(const float4*)&W[(size_t)(bn + r) * Ec + k0 + c4];
            unsigned h0, l0, h1, l1;
            split2(v.x, v.y, h0, l0);
            split2(v.z, v.w, h1, l1);
            unsigned off = r * 128 + ((c4 * 2) ^ ((r & 7) << 4));
            *(uint2*)(Whi + off) = make_uint2(h0, h1);
            *(uint2*)(Wlo + off) = make_uint2(l0, l1);
        }
        __syncthreads();

#pragma unroll
        for (int k = 0; k < 4; k++) {
            const int kb = k * 32;
            unsigned ah[4][4], al[4][4];
#pragma unroll
            for (int mt = 0; mt < 4; mt++) {
                const int row = wm * 64 + mt * 16 + a_r;
                const unsigned off = row * 128 + ((kb + a_cs) ^ ((row & 7) << 4));
                ldsm4(ah[mt], sXh + off);
                ldsm4(al[mt], sXl + off);
            }
            unsigned bh[2][2], bl[2][2];
#pragma unroll
            for (int nt = 0; nt < 2; nt++) {
                const int row = wn * 16 + nt * 8 + b_r;
                const unsigned off = row * 128 + ((kb + b_cs) ^ ((row & 7) << 4));
                ldsm2(bh[nt], sWh + off);
                ldsm2(bl[nt], sWl + off);
            }
#pragma unroll
            for (int mt = 0; mt < 4; mt++)
#pragma unroll
                for (int nt = 0; nt < 2; nt++) {
                    hmma(acc[mt][nt], ah[mt], bh[nt]);
                    hmma(acc[mt][nt], ah[mt], bl[nt]);
                    hmma(acc[mt][nt], al[mt], bh[nt]);
                }
        }
        __syncthreads();
    }

    const int lr = lane >> 2, lc = (lane & 3) << 1;
#pragma unroll
    for (int mt = 0; mt < 4; mt++)
#pragma unroll
        for (int nt = 0; nt < 2; nt++) {
            const int ncol = wn * 16 + nt * 8 + lc;
            const float2 bv = *(const float2*)&bias[bn + ncol];
            const int m0 = bm + wm * 64 + mt * 16 + lr;
#pragma unroll
            for (int half = 0; half < 2; half++) {
                const int m = m0 + half * 8;
                float2 v;
                v.x = acc[mt][nt][half * 2 + 0] + bv.x;
                v.y = acc[mt][nt][half * 2 + 1] + bv.y;
                if (SPLIT) {
                    const int bIdx = m >> 10, s = m & (Sc - 1);
                    const int h = bn >> 6;
                    *(float2*)&Y[(((size_t)bIdx * Hc + h) * Sc + s) * DKc + ncol] = v;
                } else {
                    *(float2*)&Y[(size_t)m * Ec + bn + ncol] = v;
                }
            }
        }
}

__global__ void __launch_bounds__(256, 2) gemm_qkv(
    const float* __restrict__ Xq, const float* __restrict__ Xk,
    const float* __restrict__ Xv, const float* __restrict__ Wq,
    const float* __restrict__ Wk, const float* __restrict__ Wv,
    const float* __restrict__ bq, const float* __restrict__ bk,
    const float* __restrict__ bv, float* __restrict__ Yq, float* __restrict__ Yk,
    float* __restrict__ Yv) {
    const int z = blockIdx.z;
    const float* X = (z == 0) ? Xq : (z == 1) ? Xk : Xv;
    const float* W = (z == 0) ? Wq : (z == 1) ? Wk : Wv;
    const float* b = (z == 0) ? bq : (z == 1) ? bk : bv;
    float* Y = (z == 0) ? Yq : (z == 1) ? Yk : Yv;
    tgemm_body<true>(X, W, b, Y);
}

__global__ void __launch_bounds__(256, 2) gemm_out(const float* __restrict__ X,
                                                   const float* __restrict__ W,
                                                   const float* __restrict__ bias,
                                                   float* __restrict__ Y) {
    tgemm_body<false>(X, W, bias, Y);
}

// ---------------------------------------------------------------------------
// FA2-style tensor-core attention.
// Block: 256 thr = 8 warps; q-tile 128 (warp w -> rows 16w..16w+15);
// key-tile 64. Q/K/V staged bf16 hi/lo (3-split HMMA for QK and PV).
// S accum (m16n8 layout) -> bias/mask/softmax in regs -> P packed to
// bf16x2 A-fragments directly (accumulator==A-fragment layout trick).
// V via ldmatrix.x4.trans (B = V^T). Online softmax with alpha rescale.
// Smem: Qhi 16K | Qlo 16K | Khi 8K | Klo 8K | Vhi 8K | Vlo 8K = 64 KB.
// ---------------------------------------------------------------------------
__global__ void __launch_bounds__(256, 2) attn_kernel(
    const float* __restrict__ Qp, const float* __restrict__ Kp,
    const float* __restrict__ Vp, const float* __restrict__ dist,
    const int* __restrict__ mask, const float* __restrict__ cw1,
    const float* __restrict__ cb1, const float* __restrict__ cw2,
    const float* __restrict__ cb2, float* __restrict__ Xout) {
    extern __shared__ char sma[];
    char* Qh = sma;
    char* Ql = sma + 16384;
    char* Kh = sma + 32768;
    char* Kl = sma + 40960;
    char* Vh = sma + 49152;
    char* Vl = sma + 57344;
    const unsigned sQh = smem_u32(Qh), sQl = smem_u32(Ql);
    const unsigned sKh = smem_u32(Kh), sKl = smem_u32(Kl);
    const unsigned sVh = smem_u32(Vh), sVl = smem_u32(Vl);

    const int tid = threadIdx.x, warp = tid >> 5, lane = tid & 31;
    const int lr = lane >> 2, lc = lane & 3;
    const int b = blockIdx.z, h = blockIdx.y;
    const int q0 = blockIdx.x * 128;

    const float* Qbase = Qp + ((size_t)b * Hc + h) * Sc * DKc;
    const float* Kbase = Kp + ((size_t)b * Hc + h) * Sc * DKc;
    const float* Vbase = Vp + ((size_t)b * Hc + h) * Sc * DKc;

    float w1[8], b1[8], w2[8];
#pragma unroll
    for (int t = 0; t < 8; t++) {
        w1[t] = cw1[t];
        b1[t] = cb1[t];
        w2[t] = cw2[h * Hc + t];
    }
    const float c2 = cb2[h];

    // stage Q tile 128x64 -> bf16 hi/lo swizzled (persistent)
#pragma unroll
    for (int t = 0; t < 8; t++) {
        int idx = t * 256 + tid;
        int r = idx >> 4, c4 = (idx & 15) << 2;
        float4 v = *(const float4*)&Qbase[(size_t)(q0 + r) * DKc + c4];
        unsigned h0, l0, h1, l1;
        split2(v.x, v.y, h0, l0);
        split2(v.z, v.w, h1, l1);
        unsigned off = r * 128 + ((c4 * 2) ^ ((r & 7) << 4));
        *(uint2*)(Qh + off) = make_uint2(h0, h1);
        *(uint2*)(Ql + off) = make_uint2(l0, l1);
    }

    float oacc[8][4] = {};
    float mrow0 = -INFINITY, mrow1 = -INFINITY, lrow0 = 0.f, lrow1 = 0.f;

    const int qi0 = q0 + warp * 16 + lr;
    const int qi1 = qi0 + 8;

    for (int k0 = 0; k0 < Sc; k0 += 64) {
        __syncthreads();  // prior PV reads of K/V done (also covers Q on iter 0)
        // stage K/V tiles 64x64 each
#pragma unroll
        for (int t = 0; t < 4; t++) {
            int idx = t * 256 + tid;
            int r = idx >> 4, c4 = (idx & 15) << 2;
            unsigned off = r * 128 + ((c4 * 2) ^ ((r & 7) << 4));
            float4 v = *(const float4*)&Kbase[(size_t)(k0 + r) * DKc + c4];
            unsigned h0, l0, h1, l1;
            split2(v.x, v.y, h0, l0);
            split2(v.z, v.w, h1, l1);
            *(uint2*)(Kh + off) = make_uint2(h0, h1);
            *(uint2*)(Kl + off) = make_uint2(l0, l1);
            v = *(const float4*)&Vbase[(size_t)(k0 + r) * DKc + c4];
            split2(v.x, v.y, h0, l0);
            split2(v.z, v.w, h1, l1);
            *(uint2*)(Vh + off) = make_uint2(h0, h1);
            *(uint2*)(Vl + off) = make_uint2(l0, l1);
        }
        __syncthreads();

        // ---- S = Q K^T (3-split HMMA), S tiles nt=0..7 (keys 8nt..8nt+7)
        float sacc[8][4] = {};
#pragma unroll
        for (int kk = 0; kk < 4; kk++) {
            const int kb = kk * 32;
            unsigned ah[4], al[4];
            {
                const int row = warp * 16 + (lane & 15);
                const unsigned off =
                    row * 128 + (((unsigned)(kb + ((lane >> 4) << 4))) ^ ((row & 7) << 4));
                ldsm4(ah, sQh + off);
                ldsm4(al, sQl + off);
            }
#pragma unroll
            for (int ntp = 0; ntp < 4; ntp++) {
                const int row = ntp * 16 + ((lane >> 4) << 3) + (lane & 7);
                const unsigned off =
                    row * 128 +
                    (((unsigned)(kb + (((lane >> 3) & 1) << 4))) ^ ((row & 7) << 4));
                unsigned bh[4], bl[4];
                ldsm4(bh, sKh + off);  // nt0={bh0,bh1}, nt1={bh2,bh3}
                ldsm4(bl, sKl + off);
                hmma(sacc[2 * ntp], ah, &bh[0]);
                hmma(sacc[2 * ntp], ah, &bl[0]);
                hmma(sacc[2 * ntp], al, &bh[0]);
                hmma(sacc[2 * ntp + 1], ah, &bh[2]);
                hmma(sacc[2 * ntp + 1], ah, &bl[2]);
                hmma(sacc[2 * ntp + 1], al, &bh[2]);
            }
        }

        // ---- bias * scale, mask (accumulator layout: rows lr/lr+8, cols 2lc)
        const size_t ro0 = ((size_t)b * Sc + qi0) * Sc + k0;
        const size_t ro1 = ((size_t)b * Sc + qi1) * Sc + k0;
#pragma unroll
        for (int nt = 0; nt < 8; nt++) {
            const int col = nt * 8 + lc * 2;
            float2 d0 = *(const float2*)&dist[ro0 + col];
            int2 m0 = *(const int2*)&mask[ro0 + col];
            float2 d1 = *(const float2*)&dist[ro1 + col];
            int2 m1 = *(const int2*)&mask[ro1 + col];
            float dd[4] = {d0.x, d0.y, d1.x, d1.y};
            int mm[4] = {m0.x, m0.y, m1.x, m1.y};
#pragma unroll
            for (int e = 0; e < 4; e++) {
                float bias = c2;
#pragma unroll
                for (int t = 0; t < 8; t++)
                    bias += w2[t] * fmaxf(fmaf(dd[e], w1[t], b1[t]), 0.f);
                float sv = sacc[nt][e] * 0.125f * bias;
                sacc[nt][e] = (mm[e] == 0) ? -1e9f : sv;
            }
        }

        // ---- online softmax (4-lane quad shares a row)
        float mx0 = sacc[0][0], mx1 = sacc[0][2];
#pragma unroll
        for (int nt = 0; nt < 8; nt++) {
            mx0 = fmaxf(mx0, fmaxf(sacc[nt][0], sacc[nt][1]));
            mx1 = fmaxf(mx1, fmaxf(sacc[nt][2], sacc[nt][3]));
        }
        mx0 = fmaxf(mx0, __shfl_xor_sync(0xffffffffu, mx0, 1));
        mx0 = fmaxf(mx0, __shfl_xor_sync(0xffffffffu, mx0, 2));
        mx1 = fmaxf(mx1, __shfl_xor_sync(0xffffffffu, mx1, 1));
        mx1 = fmaxf(mx1, __shfl_xor_sync(0xffffffffu, mx1, 2));
        const float mn0 = fmaxf(mrow0, mx0), mn1 = fmaxf(mrow1, mx1);
        const float al0 = __expf(mrow0 - mn0), al1 = __expf(mrow1 - mn1);
        mrow0 = mn0;
        mrow1 = mn1;
        float rs0 = 0.f, rs1 = 0.f;
#pragma unroll
        for (int nt = 0; nt < 8; nt++) {
            sacc[nt][0] = __expf(sacc[nt][0] - mn0);
            sacc[nt][1] = __expf(sacc[nt][1] - mn0);
            sacc[nt][2] = __expf(sacc[nt][2] - mn1);
            sacc[nt][3] = __expf(sacc[nt][3] - mn1);
            rs0 += sacc[nt][0] + sacc[nt][1];
            rs1 += sacc[nt][2] + sacc[nt][3];
        }
        rs0 += __shfl_xor_sync(0xffffffffu, rs0, 1);
        rs0 += __shfl_xor_sync(0xffffffffu, rs0, 2);
        rs1 += __shfl_xor_sync(0xffffffffu, rs1, 1);
        rs1 += __shfl_xor_sync(0xffffffffu, rs1, 2);
        lrow0 = lrow0 * al0 + rs0;
        lrow1 = lrow1 * al1 + rs1;
#pragma unroll
        for (int dt = 0; dt < 8; dt++) {
            oacc[dt][0] *= al0;
            oacc[dt][1] *= al0;
            oacc[dt][2] *= al1;
            oacc[dt][3] *= al1;
        }

        // ---- O += P V (3-split; P accum regs ARE the A fragments)
#pragma unroll
        for (int kk = 0; kk < 4; kk++) {
            unsigned aH[4], aL[4];
#pragma unroll
            for (int half = 0; half < 2; half++) {
                const float p0 = sacc[2 * kk + half][0];
                const float p1 = sacc[2 * kk + half][1];
                const float p2 = sacc[2 * kk + half][2];
                const float p3 = sacc[2 * kk + half][3];
                unsigned ph01 = pk2(p0, p1);
                unsigned ph23 = pk2(p2, p3);
                float r0 = p0 - __uint_as_float(ph01 << 16);
                float r1 = p1 - __uint_as_float(ph01 & 0xFFFF0000u);
                float r2 = p2 - __uint_as_float(ph23 << 16);
                float r3 = p3 - __uint_as_float(ph23 & 0xFFFF0000u);
                aH[2 * half] = ph01;
                aH[2 * half + 1] = ph23;
                aL[2 * half] = pk2(r0, r1);
                aL[2 * half + 1] = pk2(r2, r3);
            }
            // reorder: a0=tile2kk(c0c1), a1=tile2kk(c2c3), a2=tile2kk+1(c0c1), a3=...
            unsigned Ah[4] = {aH[0], aH[1], aH[2], aH[3]};
            unsigned Al[4] = {aL[0], aL[1], aL[2], aL[3]};
#pragma unroll
            for (int dtp = 0; dtp < 4; dtp++) {
                const int row = kk * 16 + (lane & 15);
                const unsigned off =
                    row * 128 +
                    (((unsigned)(dtp * 32 + ((lane >> 4) << 4))) ^ ((row & 7) << 4));
                unsigned bhv[4], blv[4];
                ldsm4t(bhv, sVh + off);  // dt0={b0,b1}, dt1={b2,b3}
                ldsm4t(blv, sVl + off);
                hmma(oacc[2 * dtp], Ah, &bhv[0]);
                hmma(oacc[2 * dtp], Ah, &blv[0]);
                hmma(oacc[2 * dtp], Al, &bhv[0]);
                hmma(oacc[2 * dtp + 1], Ah, &bhv[2]);
                hmma(oacc[2 * dtp + 1], Ah, &blv[2]);
                hmma(oacc[2 * dtp + 1], Al, &bhv[2]);
            }
        }
    }

    // epilogue: normalize, write concatenated [B,S,E]
    const float inv0 = 1.f / lrow0, inv1 = 1.f / lrow1;
#pragma unroll
    for (int dt = 0; dt < 8; dt++) {
        const int col = h * DKc + dt * 8 + lc * 2;
        float2 v0 = {oacc[dt][0] * inv0, oacc[dt][1] * inv0};
        float2 v1 = {oacc[dt][2] * inv1, oacc[dt][3] * inv1};
        *(float2*)&Xout[((size_t)b * Sc + qi0) * Ec + col] = v0;
        *(float2*)&Xout[((size_t)b * Sc + qi1) * Ec + col] = v1;
    }
}

// ---------------------------------------------------------------------------

extern "C" void kernel_launch(void* const* d_in, const int* in_sizes, int n_in,
                              void* d_out, int out_size) {
    const float* query = (const float*)d_in[0];
    const float* key   = (const float*)d_in[1];
    const float* value = (const float*)d_in[2];
    const float* dist  = (const float*)d_in[3];
    const int*   mask  = (const int*)d_in[4];
    const float* Wq = (const float*)d_in[5];
    const float* bq = (const float*)d_in[6];
    const float* Wk = (const float*)d_in[7];
    const float* bk = (const float*)d_in[8];
    const float* Wv = (const float*)d_in[9];
    const float* bv = (const float*)d_in[10];
    const float* Wo = (const float*)d_in[11];
    const float* bo = (const float*)d_in[12];
    const float* cw1 = (const float*)d_in[13];
    const float* cb1 = (const float*)d_in[14];
    const float* cw2 = (const float*)d_in[15];
    const float* cb2 = (const float*)d_in[16];
    float* out = (float*)d_out;

    float *Qp, *Kp, *Vp, *Xc;
    cudaGetSymbolAddress((void**)&Qp, g_Q);
    cudaGetSymbolAddress((void**)&Kp, g_K);
    cudaGetSymbolAddress((void**)&Vp, g_V);
    cudaGetSymbolAddress((void**)&Xc, g_X);

    const int gsmem = 49152;  // bytes
    cudaFuncSetAttribute(gemm_qkv, cudaFuncAttributeMaxDynamicSharedMemorySize, gsmem);
    cudaFuncSetAttribute(gemm_out, cudaFuncAttributeMaxDynamicSharedMemorySize, gsmem);

    gemm_qkv<<<dim3(Ec / 64, M_TOT / 128, 3), 256, gsmem>>>(
        query, key, value, Wq, Wk, Wv, bq, bk, bv, Qp, Kp, Vp);

    const int asmem = 65536;  // bytes
    cudaFuncSetAttribute(attn_kernel, cudaFuncAttributeMaxDynamicSharedMemorySize, asmem);
    attn_kernel<<<dim3(Sc / 128, Hc, Bc), 256, asmem>>>(Qp, Kp, Vp, dist, mask, cw1,
                                                        cb1, cw2, cb2, Xc);

    gemm_out<<<dim3(Ec / 64, M_TOT / 128, 1), 256, gsmem>>>(Xc, Wo, bo, out);
}